// round 14
// baseline (speedup 1.0000x reference)
#include <cuda_runtime.h>
#include <cuda_bf16.h>
#include <math.h>
#include <stdint.h>

// ---------------------------------------------------------------------------
// Scratch (device globals; no dynamic allocation allowed)
// ---------------------------------------------------------------------------
__device__ uint16_t g_wq[3072 * 1024];        // qkv_w  bf16 [o][k]
__device__ uint16_t g_wp[1024 * 1024];        // proj_w bf16 [o][k]
__device__ uint32_t g_xnp[4 * 512 * 1024];    // xn  packed bf16 pairs [b][c/2][t]
__device__ uint16_t g_qkvb[4 * 3072 * 1024];  // qkv bf16 [b][3C][t]
__device__ uint32_t g_attnp[4 * 512 * 1024];  // attn packed bf16 pairs [b][c/2][t]
__device__ float    g_stats[1024];            // gn partial sums [bg][8]
__device__ unsigned g_ticket;                 // persistent-GEMM work ticket

// ---------------------------------------------------------------------------
// helpers
// ---------------------------------------------------------------------------
__device__ __forceinline__ uint32_t smem_u32(const void* p) {
    uint32_t a;
    asm("{ .reg .u64 t; cvta.to.shared.u64 t, %1; cvt.u32.u64 %0, t; }" : "=r"(a) : "l"(p));
    return a;
}
__device__ __forceinline__ uint32_t bfpack(float lo, float hi) {
    uint32_t r;
    asm("cvt.rn.bf16x2.f32 %0, %1, %2;" : "=r"(r) : "f"(hi), "f"(lo));
    return r;
}
__device__ __forceinline__ uint16_t bfu(float x) {
    uint16_t r;
    asm("cvt.rn.bf16.f32 %0, %1;" : "=h"(r) : "f"(x));
    return r;
}
__device__ __forceinline__ float ubf(uint32_t bits16) {
    return __uint_as_float(bits16 << 16);
}
__device__ __forceinline__ void cp16(uint32_t dst, const void* src) {
    asm volatile("cp.async.cg.shared.global [%0], [%1], 16;" :: "r"(dst), "l"(src));
}
__device__ __forceinline__ void cp_commit() { asm volatile("cp.async.commit_group;"); }
__device__ __forceinline__ void cp_wait0() { asm volatile("cp.async.wait_group 0;" ::: "memory"); }
__device__ __forceinline__ void cp_wait1() { asm volatile("cp.async.wait_group 1;" ::: "memory"); }

// bf16 MMA m16n8k16
__device__ __forceinline__ void mma_bf16(float* c, const uint32_t* a, const uint32_t* b) {
    asm volatile(
        "mma.sync.aligned.m16n8k16.row.col.f32.bf16.bf16.f32 "
        "{%0,%1,%2,%3}, {%4,%5,%6,%7}, {%8,%9}, {%0,%1,%2,%3};"
        : "+f"(c[0]), "+f"(c[1]), "+f"(c[2]), "+f"(c[3])
        : "r"(a[0]), "r"(a[1]), "r"(a[2]), "r"(a[3]), "r"(b[0]), "r"(b[1]));
}
__device__ __forceinline__ void ldsm_x4(uint32_t* r, uint32_t addr) {
    asm volatile("ldmatrix.sync.aligned.m8n8.x4.shared.b16 {%0,%1,%2,%3}, [%4];"
                 : "=r"(r[0]), "=r"(r[1]), "=r"(r[2]), "=r"(r[3]) : "r"(addr));
}

// ---------------------------------------------------------------------------
// Weight conversion fp32 -> bf16 (both weights in one launch)
// ---------------------------------------------------------------------------
__global__ void conv_w2(const float* __restrict__ s1, uint32_t* __restrict__ d1, int n1,
                        const float* __restrict__ s2, uint32_t* __restrict__ d2) {
    int i = blockIdx.x * 256 + threadIdx.x;
    const float4* src;
    uint2* dst;
    int j;
    if (i < n1) { src = (const float4*)s1; dst = (uint2*)d1; j = i; }
    else        { src = (const float4*)s2; dst = (uint2*)d2; j = i - n1; }
    float4 v = src[j];
    uint2 o;
    o.x = bfpack(v.x, v.y);
    o.y = bfpack(v.z, v.w);
    dst[j] = o;
}

// ---------------------------------------------------------------------------
// GroupNorm phase 1: partial sums per (b, g, t-quarter). 512 blocks.
// ---------------------------------------------------------------------------
__global__ __launch_bounds__(256) void gn_part(const float* __restrict__ x,
                                               float* __restrict__ stats) {
    int bid = blockIdx.x;
    int tq = bid & 3, g = (bid >> 2) & 31, b = bid >> 7;
    const float4* xp = (const float4*)(x + ((size_t)(b * 1024 + g * 32)) * 1024);

    float s = 0.f, ss = 0.f;
#pragma unroll
    for (int r = 0; r < 8; r++) {
        int u = r * 256 + threadIdx.x;     // 0..2047
        int c = u >> 6, t4 = tq * 64 + (u & 63);
        float4 v = xp[c * 256 + t4];
        s += v.x + v.y + v.z + v.w;
        ss += v.x * v.x + v.y * v.y + v.z * v.z + v.w * v.w;
    }
#pragma unroll
    for (int o = 16; o; o >>= 1) {
        s  += __shfl_xor_sync(0xffffffffu, s, o);
        ss += __shfl_xor_sync(0xffffffffu, ss, o);
    }
    __shared__ float red[16];
    int warp = threadIdx.x >> 5, lane = threadIdx.x & 31;
    if (lane == 0) { red[warp] = s; red[warp + 8] = ss; }
    __syncthreads();
    if (threadIdx.x == 0) {
        float ts = 0.f, tss = 0.f;
#pragma unroll
        for (int i = 0; i < 8; i++) { ts += red[i]; tss += red[i + 8]; }
        int bg = b * 32 + g;
        stats[bg * 8 + tq] = ts;
        stats[bg * 8 + 4 + tq] = tss;
    }
}

// ---------------------------------------------------------------------------
// GroupNorm phase 2: normalize + write packed bf16. 512 blocks (x in L2).
// ---------------------------------------------------------------------------
__global__ __launch_bounds__(256) void gn_norm(const float* __restrict__ x,
                                               const float* __restrict__ w,
                                               const float* __restrict__ b_,
                                               const float* __restrict__ stats,
                                               uint32_t* __restrict__ xnp) {
    int bid = blockIdx.x;
    int tq = bid & 3, g = (bid >> 2) & 31, b = bid >> 7;
    int bg = b * 32 + g;
    float ts = stats[bg * 8] + stats[bg * 8 + 1] + stats[bg * 8 + 2] + stats[bg * 8 + 3];
    float tss = stats[bg * 8 + 4] + stats[bg * 8 + 5] + stats[bg * 8 + 6] + stats[bg * 8 + 7];
    float mu = ts * (1.f / 32768.f);
    float inv = rsqrtf(tss * (1.f / 32768.f) - mu * mu + 1e-5f);

    const float4* xp = (const float4*)(x + ((size_t)(b * 1024 + g * 32)) * 1024);
#pragma unroll
    for (int r = 0; r < 4; r++) {
        int u = r * 256 + threadIdx.x;     // 0..1023
        int cp = u >> 6, t4 = tq * 64 + (u & 63);
        int c0 = g * 32 + 2 * cp, c1 = c0 + 1;
        float s0 = inv * w[c0], h0 = b_[c0] - mu * s0;
        float s1 = inv * w[c1], h1 = b_[c1] - mu * s1;
        float4 va = xp[(2 * cp) * 256 + t4];
        float4 vb = xp[(2 * cp + 1) * 256 + t4];
        uint4 o;
        o.x = bfpack(va.x * s0 + h0, vb.x * s1 + h1);
        o.y = bfpack(va.y * s0 + h0, vb.y * s1 + h1);
        o.z = bfpack(va.z * s0 + h0, vb.z * s1 + h1);
        o.w = bfpack(va.w * s0 + h0, vb.w * s1 + h1);
        ((uint4*)(xnp + ((size_t)(b * 512 + g * 16 + cp)) * 1024))[t4] = o;
    }
}

// ---------------------------------------------------------------------------
// bf16 tensor-core GEMM: K-tile 32, ldmatrix A fragments, 3-stage cp.async.
// PERSIST: 296 CTAs pull tiles from a global ticket (removes wave tail).
// ---------------------------------------------------------------------------
#define APW 20
#define BPW 136
#define STG_W (128 * APW + 16 * BPW)
#define GEMM_SMEM (3 * STG_W * 4)

template <bool BF16OUT, bool PERSIST>
__global__ __launch_bounds__(256, 2) void gemm_bf16(const uint16_t* __restrict__ Wb,
                                                    const uint32_t* __restrict__ Xp,
                                                    const float* __restrict__ bias,
                                                    const float* __restrict__ R,
                                                    void* __restrict__ outv, int O,
                                                    int nTiles) {
    extern __shared__ float sm[];
    __shared__ unsigned s_idx;

    const int tid = threadIdx.x;
    const int wid = tid >> 5, lane = tid & 31;
    const int gid = lane >> 2, tg = lane & 3;
    const int warp_m = (wid & 3) * 32, warp_n = (wid >> 2) * 64;
    const uint32_t aS = smem_u32(sm);
    const int lrow = lane & 15, lkw = (lane >> 4) * 4;

    auto run_tile = [&](int t0, int o0, int z) {
        const uint32_t* Xb = Xp + (size_t)z * 512 * 1024;

        float c[2][8][4];
#pragma unroll
        for (int mt = 0; mt < 2; mt++)
#pragma unroll
            for (int nt = 0; nt < 8; nt++)
#pragma unroll
                for (int e = 0; e < 4; e++) c[mt][nt][e] = 0.f;

        auto issue = [&](int s, int kt) {
            const int k0 = kt * 32;
            const int kp0 = kt * 16;
            uint32_t bA = aS + (uint32_t)(s * STG_W * 4);
            uint32_t bB = bA + (uint32_t)(128 * APW * 4);
#pragma unroll
            for (int i = 0; i < 2; i++) {
                int id = tid * 2 + i;
                int row = id >> 2, gr = id & 3;
                cp16(bA + (uint32_t)(row * APW * 4 + gr * 16),
                     Wb + (size_t)(o0 + row) * 1024 + k0 + gr * 8);
            }
#pragma unroll
            for (int i = 0; i < 2; i++) {
                int id = tid * 2 + i;
                int row = id >> 5, gw = id & 31;
                cp16(bB + (uint32_t)(row * BPW * 4 + gw * 16),
                     Xb + (size_t)(kp0 + row) * 1024 + t0 + gw * 4);
            }
            cp_commit();
        };

        issue(0, 0);
        issue(1, 1);

        int stage = 0;
        for (int kt = 0; kt < 32; kt++) {
            if (kt + 1 < 32) cp_wait1(); else cp_wait0();
            __syncthreads();
            if (kt + 2 < 32) issue(stage == 0 ? 2 : stage - 1, kt + 2);

            const uint32_t aWb = aS + (uint32_t)(stage * STG_W * 4);
            const uint32_t* xb = (const uint32_t*)sm + stage * STG_W + 128 * APW;

#pragma unroll
            for (int ks = 0; ks < 2; ks++) {
                const int kw = ks * 8;
                uint32_t af[2][4];
#pragma unroll
                for (int mt = 0; mt < 2; mt++) {
                    uint32_t addr = aWb +
                        (uint32_t)(((warp_m + mt * 16 + lrow) * APW + kw + lkw) * 4);
                    ldsm_x4(af[mt], addr);
                }
                uint32_t bf[8][2];
#pragma unroll
                for (int nt = 0; nt < 8; nt++) {
                    const uint32_t* xr = xb + (kw + tg) * BPW + warp_n + nt * 8 + gid;
                    bf[nt][0] = xr[0];
                    bf[nt][1] = xr[4 * BPW];
                }
#pragma unroll
                for (int mt = 0; mt < 2; mt++)
#pragma unroll
                    for (int nt = 0; nt < 8; nt++)
                        mma_bf16(c[mt][nt], af[mt], bf[nt]);
            }
            stage = (stage == 2) ? 0 : stage + 1;
        }

#pragma unroll
        for (int mt = 0; mt < 2; mt++) {
#pragma unroll
            for (int half = 0; half < 2; half++) {
                int o = o0 + warp_m + mt * 16 + gid + half * 8;
                float bv = bias[o];
                size_t rowbase = ((size_t)z * O + o) * 1024;
#pragma unroll
                for (int nt = 0; nt < 8; nt++) {
                    int t = t0 + warp_n + nt * 8 + tg * 2;
                    float vx = c[mt][nt][half * 2 + 0] + bv;
                    float vy = c[mt][nt][half * 2 + 1] + bv;
                    if (BF16OUT) {
                        ((uint32_t*)outv)[(rowbase + t) >> 1] = bfpack(vx, vy);
                    } else {
                        float2 rr = *(const float2*)(R + rowbase + t);
                        float2 v = { vx + rr.x, vy + rr.y };
                        *(float2*)((float*)outv + rowbase + t) = v;
                    }
                }
            }
        }
    };

    if (!PERSIST) {
        run_tile(blockIdx.x * 128, blockIdx.y * 128, blockIdx.z);
    } else {
        for (;;) {
            if (tid == 0) s_idx = atomicAdd(&g_ticket, 1u);
            __syncthreads();
            unsigned idx = s_idx;
            if (idx >= (unsigned)nTiles) break;
            int z = idx / 192;
            int rem = idx - z * 192;
            run_tile((rem & 7) * 128, (rem >> 3) * 128, z);
            __syncthreads();
        }
    }
}

// ---------------------------------------------------------------------------
// Flash attention, bf16 mma, Q-tile 128, double-buffered K/V in smem:
// ONE __syncthreads per 64-key tile.
// ---------------------------------------------------------------------------
#define TPW 36
#define ATTN_SMEM (512 * TPW * 4)

__global__ __launch_bounds__(256, 2) void attn_mma(const uint16_t* __restrict__ qkvb,
                                                   uint32_t* __restrict__ attnp) {
    extern __shared__ float smf[];
    uint32_t* Qt = (uint32_t*)smf;          // [128 i][TPW]
    uint32_t* St = Qt + 128 * TPW;          // [128 i][TPW]
    uint32_t* Kt = St + 128 * TPW;          // [2][64 j][TPW]
    uint32_t* Vs = Kt + 128 * TPW;          // [2][64 c][TPW]

    const int bh = blockIdx.y;
    const int b = bh >> 4, h = bh & 15;
    const int t0 = blockIdx.x * 128;
    const uint16_t* qg = qkvb + ((size_t)b * 3072 + h * 192) * 1024;
    const uint16_t* kg = qg + 64 * 1024;
    const uint32_t* vg = (const uint32_t*)(qg + 128 * 1024);

    const int tid = threadIdx.x, wid = tid >> 5, lane = tid & 31;
    const int gid = lane >> 2, tg = lane & 3;
    const int i0 = wid * 16;

    const uint32_t aQt = smem_u32(Qt), aKt = smem_u32(Kt);
    const uint32_t aVs = smem_u32(Vs), aSt = smem_u32(St);
    const int lrow = lane & 15, lkw = (lane >> 4) * 4;
    const uint32_t bOffB = (uint32_t)(((i0 + ((lane >> 4) << 3) + (lane & 7)) * TPW
                                       + ((lane >> 3) & 1) * 4) * 4);

    // Q tile: Qt[i][cpair], 128 rows
#pragma unroll
    for (int r = 0; r < 16; r++) {
        int u = r * 256 + tid;
        int i = u & 127, cp = u >> 7;
        uint32_t lo = qg[(size_t)(2 * cp) * 1024 + t0 + i];
        uint32_t hi = qg[(size_t)(2 * cp + 1) * 1024 + t0 + i];
        Qt[i * TPW + cp] = lo | (hi << 16);
    }

    uint32_t kwr[8], vwr[8];
    auto ldg_tile = [&](int s0) {
#pragma unroll
        for (int r = 0; r < 8; r++) {
            int u = r * 256 + tid;
            int j = u & 63, cp = u >> 6;
            uint32_t lo = kg[(size_t)(2 * cp) * 1024 + s0 + j];
            uint32_t hi = kg[(size_t)(2 * cp + 1) * 1024 + s0 + j];
            kwr[r] = lo | (hi << 16);
            int cc = u >> 5, jw = u & 31;
            vwr[r] = vg[((size_t)cc * 1024 + s0) / 2 + jw];
        }
    };
    auto store_kv = [&](int buf) {
        uint32_t* kb = Kt + buf * 64 * TPW;
        uint32_t* vb = Vs + buf * 64 * TPW;
#pragma unroll
        for (int r = 0; r < 8; r++) {
            int u = r * 256 + tid;
            int j = u & 63, cp = u >> 6;
            kb[j * TPW + cp] = kwr[r];
            int cc = u >> 5, jw = u & 31;
            vb[cc * TPW + jw] = vwr[r];
        }
    };

    float o[2][4][4];
#pragma unroll
    for (int q = 0; q < 2; q++)
#pragma unroll
        for (int mt = 0; mt < 4; mt++)
#pragma unroll
            for (int e = 0; e < 4; e++) o[q][mt][e] = 0.f;
    float m_run[2][2] = { { -1e30f, -1e30f }, { -1e30f, -1e30f } };
    float l_run[2][2] = { { 0.f, 0.f }, { 0.f, 0.f } };

    ldg_tile(0);
    store_kv(0);
    __syncthreads();

    for (int t = 0; t < 16; t++) {
        const int buf = t & 1;
        const uint32_t kOff = (uint32_t)(buf * 64 * TPW * 4);
        if (t + 1 < 16) ldg_tile((t + 1) * 64);

        // ---- S = Kt * Q ----
        float sc[2][4][4];
#pragma unroll
        for (int q = 0; q < 2; q++)
#pragma unroll
            for (int mt = 0; mt < 4; mt++)
#pragma unroll
                for (int e = 0; e < 4; e++) sc[q][mt][e] = 0.f;

#pragma unroll
        for (int ks = 0; ks < 4; ks++) {
            uint32_t bb[4];
            ldsm_x4(bb, aQt + bOffB + (uint32_t)(ks * 32));
#pragma unroll
            for (int mt = 0; mt < 4; mt++) {
                uint32_t a[4];
                ldsm_x4(a, aKt + kOff + (uint32_t)(((mt * 16 + lrow) * TPW + lkw) * 4 + ks * 32));
                mma_bf16(sc[0][mt], a, bb);
                mma_bf16(sc[1][mt], a, bb + 2);
            }
        }

        // ---- warp-local online softmax ----
        float alpha[2][2], psum[2][2];
#pragma unroll
        for (int q = 0; q < 2; q++) {
#pragma unroll
            for (int e = 0; e < 2; e++) {
                float cm = fmaxf(fmaxf(sc[q][0][e], sc[q][0][e + 2]),
                                 fmaxf(sc[q][1][e], sc[q][1][e + 2]));
                cm = fmaxf(cm, fmaxf(fmaxf(sc[q][2][e], sc[q][2][e + 2]),
                                     fmaxf(sc[q][3][e], sc[q][3][e + 2])));
                cm *= 0.125f;
#pragma unroll
                for (int mk = 4; mk <= 16; mk <<= 1)
                    cm = fmaxf(cm, __shfl_xor_sync(0xffffffffu, cm, mk));
                float mn = fmaxf(m_run[q][e], cm);
                alpha[q][e] = __expf(m_run[q][e] - mn);
                m_run[q][e] = mn;
                psum[q][e] = 0.f;
            }
        }
#pragma unroll
        for (int q = 0; q < 2; q++) {
#pragma unroll
            for (int mt = 0; mt < 4; mt++) {
#pragma unroll
                for (int e = 0; e < 2; e++) {
                    uint32_t h0 = bfu(__expf(sc[q][mt][e] * 0.125f - m_run[q][e]));
                    uint32_t h1 = bfu(__expf(sc[q][mt][e + 2] * 0.125f - m_run[q][e]));
                    psum[q][e] += ubf(h0) + ubf(h1);
                    uint32_t w = h0 | (h1 << 16);
                    uint32_t pw = __shfl_xor_sync(0xffffffffu, w, 4);
                    if ((gid & 1) == 0) {
                        int i = i0 + 8 * q + 2 * tg + e;
                        St[i * TPW + (mt * 16 + gid) / 2] = (w & 0xffffu) | (pw << 16);
                        St[i * TPW + (mt * 16 + gid + 8) / 2] = (w >> 16) | (pw & 0xffff0000u);
                    }
                }
            }
        }
#pragma unroll
        for (int q = 0; q < 2; q++) {
#pragma unroll
            for (int e = 0; e < 2; e++) {
#pragma unroll
                for (int mk = 4; mk <= 16; mk <<= 1)
                    psum[q][e] += __shfl_xor_sync(0xffffffffu, psum[q][e], mk);
                l_run[q][e] = l_run[q][e] * alpha[q][e] + psum[q][e];
            }
#pragma unroll
            for (int mt = 0; mt < 4; mt++) {
                o[q][mt][0] *= alpha[q][0]; o[q][mt][2] *= alpha[q][0];
                o[q][mt][1] *= alpha[q][1]; o[q][mt][3] *= alpha[q][1];
            }
        }
        __syncwarp();

        // ---- O += V * P ----
#pragma unroll
        for (int ks = 0; ks < 4; ks++) {
            uint32_t bb[4];
            ldsm_x4(bb, aSt + bOffB + (uint32_t)(ks * 32));
#pragma unroll
            for (int mt = 0; mt < 4; mt++) {
                uint32_t a[4];
                ldsm_x4(a, aVs + kOff + (uint32_t)(((mt * 16 + lrow) * TPW + lkw) * 4 + ks * 32));
                mma_bf16(o[0][mt], a, bb);
                mma_bf16(o[1][mt], a, bb + 2);
            }
        }

        if (t + 1 < 16) store_kv(buf ^ 1);
        __syncthreads();
    }

    // normalize + write packed bf16 pairs over c
#pragma unroll
    for (int q = 0; q < 2; q++) {
        float li0 = 1.f / l_run[q][0], li1 = 1.f / l_run[q][1];
#pragma unroll
        for (int mt = 0; mt < 4; mt++) {
#pragma unroll
            for (int e = 0; e < 2; e++) {
                float li = e ? li1 : li0;
                uint32_t b0 = bfu(o[q][mt][e] * li);
                uint32_t b1 = bfu(o[q][mt][e + 2] * li);
                uint32_t w = b0 | (b1 << 16);
                uint32_t pw = __shfl_xor_sync(0xffffffffu, w, 4);
                if ((gid & 1) == 0) {
                    int i = t0 + i0 + 8 * q + 2 * tg + e;
                    int c = h * 64 + mt * 16 + gid;
                    attnp[((size_t)b * 512 + c / 2) * 1024 + i] = (w & 0xffffu) | (pw << 16);
                    attnp[((size_t)b * 512 + (c + 8) / 2) * 1024 + i] = (w >> 16) | (pw & 0xffff0000u);
                }
            }
        }
    }
}

// ---------------------------------------------------------------------------
extern "C" void kernel_launch(void* const* d_in, const int* in_sizes, int n_in,
                              void* d_out, int out_size) {
    const float* x      = (const float*)d_in[0];
    const float* nw     = (const float*)d_in[1];
    const float* nb     = (const float*)d_in[2];
    const float* qkv_w  = (const float*)d_in[3];
    const float* qkv_b  = (const float*)d_in[4];
    const float* proj_w = (const float*)d_in[5];
    const float* proj_b = (const float*)d_in[6];
    float* out = (float*)d_out;

    uint16_t *wq, *wp, *qkvb;
    uint32_t *xnp, *attnp;
    float* stats;
    unsigned* ticket;
    cudaGetSymbolAddress((void**)&wq,     g_wq);
    cudaGetSymbolAddress((void**)&wp,     g_wp);
    cudaGetSymbolAddress((void**)&xnp,    g_xnp);
    cudaGetSymbolAddress((void**)&qkvb,   g_qkvb);
    cudaGetSymbolAddress((void**)&attnp,  g_attnp);
    cudaGetSymbolAddress((void**)&stats,  g_stats);
    cudaGetSymbolAddress((void**)&ticket, g_ticket);

    // reset persistent-GEMM ticket (async memset node; graph-capturable)
    cudaMemsetAsync(ticket, 0, sizeof(unsigned));

    // 0. Weight conversion to bf16 (both in one launch)
    conv_w2<<<4096, 256>>>(qkv_w, (uint32_t*)wq, 786432, proj_w, (uint32_t*)wp);

    // 1. GroupNorm (two-phase, 512 blocks each) -> packed bf16
    gn_part<<<512, 256>>>(x, stats);
    gn_norm<<<512, 256>>>(x, nw, nb, stats, xnp);

    // 2. QKV projection (bf16 mma, persistent 296 CTAs over 768 tiles) -> bf16
    cudaFuncSetAttribute(gemm_bf16<true, true>,
                         cudaFuncAttributeMaxDynamicSharedMemorySize, GEMM_SMEM);
    gemm_bf16<true, true><<<296, 256, GEMM_SMEM>>>(wq, xnp, qkv_b, nullptr, qkvb, 3072, 768);

    // 3. Attention (bf16 mma flash, Q-tile 128, 1 sync/tile) -> packed bf16
    cudaFuncSetAttribute(attn_mma, cudaFuncAttributeMaxDynamicSharedMemorySize, ATTN_SMEM);
    attn_mma<<<dim3(8, 64), 256, ATTN_SMEM>>>(qkvb, attnp);

    // 4. Output projection + bias + residual (fp32 out)
    cudaFuncSetAttribute(gemm_bf16<false, false>,
                         cudaFuncAttributeMaxDynamicSharedMemorySize, GEMM_SMEM);
    gemm_bf16<false, false><<<dim3(8, 8, 4), 256, GEMM_SMEM>>>(wp, attnp, proj_b, x, out, 1024, 0);
}

// round 15
// speedup vs baseline: 1.0449x; 1.0449x over previous
#include <cuda_runtime.h>
#include <cuda_bf16.h>
#include <math.h>
#include <stdint.h>

// ---------------------------------------------------------------------------
// Scratch (device globals; no dynamic allocation allowed)
// ---------------------------------------------------------------------------
__device__ uint16_t g_wq[3072 * 1024];        // qkv_w  bf16 [o][k]
__device__ uint16_t g_wp[1024 * 1024];        // proj_w bf16 [o][k]
__device__ uint32_t g_xnp[4 * 512 * 1024];    // xn  packed bf16 pairs [b][c/2][t]
__device__ uint16_t g_qkvb[4 * 3072 * 1024];  // qkv bf16 [b][3C][t]
__device__ uint32_t g_attnp[4 * 512 * 1024];  // attn packed bf16 pairs [b][c/2][t]

// ---------------------------------------------------------------------------
// helpers
// ---------------------------------------------------------------------------
__device__ __forceinline__ uint32_t smem_u32(const void* p) {
    uint32_t a;
    asm("{ .reg .u64 t; cvta.to.shared.u64 t, %1; cvt.u32.u64 %0, t; }" : "=r"(a) : "l"(p));
    return a;
}
__device__ __forceinline__ uint32_t bfpack(float lo, float hi) {
    uint32_t r;
    asm("cvt.rn.bf16x2.f32 %0, %1, %2;" : "=r"(r) : "f"(hi), "f"(lo));
    return r;
}
__device__ __forceinline__ uint16_t bfu(float x) {
    uint16_t r;
    asm("cvt.rn.bf16.f32 %0, %1;" : "=h"(r) : "f"(x));
    return r;
}
__device__ __forceinline__ float ubf(uint32_t bits16) {
    return __uint_as_float(bits16 << 16);
}
__device__ __forceinline__ void cp16(uint32_t dst, const void* src) {
    asm volatile("cp.async.cg.shared.global [%0], [%1], 16;" :: "r"(dst), "l"(src));
}
__device__ __forceinline__ void cp_commit() { asm volatile("cp.async.commit_group;"); }
__device__ __forceinline__ void cp_wait0() { asm volatile("cp.async.wait_group 0;" ::: "memory"); }
__device__ __forceinline__ void cp_wait1() { asm volatile("cp.async.wait_group 1;" ::: "memory"); }

// bf16 MMA m16n8k16
__device__ __forceinline__ void mma_bf16(float* c, const uint32_t* a, const uint32_t* b) {
    asm volatile(
        "mma.sync.aligned.m16n8k16.row.col.f32.bf16.bf16.f32 "
        "{%0,%1,%2,%3}, {%4,%5,%6,%7}, {%8,%9}, {%0,%1,%2,%3};"
        : "+f"(c[0]), "+f"(c[1]), "+f"(c[2]), "+f"(c[3])
        : "r"(a[0]), "r"(a[1]), "r"(a[2]), "r"(a[3]), "r"(b[0]), "r"(b[1]));
}
__device__ __forceinline__ void ldsm_x4(uint32_t* r, uint32_t addr) {
    asm volatile("ldmatrix.sync.aligned.m8n8.x4.shared.b16 {%0,%1,%2,%3}, [%4];"
                 : "=r"(r[0]), "=r"(r[1]), "=r"(r[2]), "=r"(r[3]) : "r"(addr));
}

// ---------------------------------------------------------------------------
// Weight conversion fp32 -> bf16 (both weights in one launch)
// ---------------------------------------------------------------------------
__global__ void conv_w2(const float* __restrict__ s1, uint32_t* __restrict__ d1, int n1,
                        const float* __restrict__ s2, uint32_t* __restrict__ d2) {
    int i = blockIdx.x * 256 + threadIdx.x;
    const float4* src;
    uint2* dst;
    int j;
    if (i < n1) { src = (const float4*)s1; dst = (uint2*)d1; j = i; }
    else        { src = (const float4*)s2; dst = (uint2*)d2; j = i - n1; }
    float4 v = src[j];
    uint2 o;
    o.x = bfpack(v.x, v.y);
    o.y = bfpack(v.z, v.w);
    dst[j] = o;
}

// ---------------------------------------------------------------------------
// GroupNorm: one block per (batch, group); writes c-pair-packed bf16.
// ---------------------------------------------------------------------------
__global__ __launch_bounds__(1024) void gn_kernel(const float* __restrict__ x,
                                                  const float* __restrict__ w,
                                                  const float* __restrict__ b,
                                                  uint32_t* __restrict__ xnp) {
    int batch = blockIdx.x >> 5;
    int g = blockIdx.x & 31;
    const float4* xp = (const float4*)(x + ((size_t)batch * 1024 + g * 32) * 1024);

    float4 va[4], vb[4];
    float s = 0.f, ss = 0.f;
#pragma unroll
    for (int r = 0; r < 4; r++) {
        int u = r * 1024 + threadIdx.x;
        int cp = u >> 8, t4 = u & 255;
        va[r] = xp[cp * 512 + t4];
        vb[r] = xp[cp * 512 + 256 + t4];
        s += va[r].x + va[r].y + va[r].z + va[r].w + vb[r].x + vb[r].y + vb[r].z + vb[r].w;
        ss += va[r].x * va[r].x + va[r].y * va[r].y + va[r].z * va[r].z + va[r].w * va[r].w
            + vb[r].x * vb[r].x + vb[r].y * vb[r].y + vb[r].z * vb[r].z + vb[r].w * vb[r].w;
    }
#pragma unroll
    for (int o = 16; o; o >>= 1) {
        s  += __shfl_xor_sync(0xffffffffu, s, o);
        ss += __shfl_xor_sync(0xffffffffu, ss, o);
    }
    __shared__ float red[66];
    int warp = threadIdx.x >> 5, lane = threadIdx.x & 31;
    if (lane == 0) { red[warp] = s; red[warp + 32] = ss; }
    __syncthreads();
    if (threadIdx.x == 0) {
        float ts = 0.f, tss = 0.f;
#pragma unroll
        for (int i = 0; i < 32; i++) { ts += red[i]; tss += red[i + 32]; }
        float mu = ts * (1.f / 32768.f);
        float var = tss * (1.f / 32768.f) - mu * mu;
        red[64] = mu;
        red[65] = rsqrtf(var + 1e-5f);
    }
    __syncthreads();
    float mu = red[64], inv = red[65];
#pragma unroll
    for (int r = 0; r < 4; r++) {
        int u = r * 1024 + threadIdx.x;
        int cp = u >> 8, t4 = u & 255;
        int c0 = g * 32 + 2 * cp, c1 = c0 + 1;
        float s0 = inv * w[c0], h0 = b[c0] - mu * s0;
        float s1 = inv * w[c1], h1 = b[c1] - mu * s1;
        uint4 o;
        o.x = bfpack(va[r].x * s0 + h0, vb[r].x * s1 + h1);
        o.y = bfpack(va[r].y * s0 + h0, vb[r].y * s1 + h1);
        o.z = bfpack(va[r].z * s0 + h0, vb[r].z * s1 + h1);
        o.w = bfpack(va[r].w * s0 + h0, vb[r].w * s1 + h1);
        ((uint4*)(xnp + ((size_t)(batch * 512 + g * 16 + cp)) * 1024))[t4] = o;
    }
}

// ---------------------------------------------------------------------------
// bf16 tensor-core GEMM: K-tile 32, ldmatrix A fragments, 3-stage cp.async
// ring with ONE __syncthreads per k-tile. (R13 configuration, best measured.)
// ---------------------------------------------------------------------------
#define APW 20
#define BPW 136
#define STG_W (128 * APW + 16 * BPW)
#define GEMM_SMEM (3 * STG_W * 4)

template <bool BF16OUT>
__global__ __launch_bounds__(256, 2) void gemm_bf16(const uint16_t* __restrict__ Wb,
                                                    const uint32_t* __restrict__ Xp,
                                                    const float* __restrict__ bias,
                                                    const float* __restrict__ R,
                                                    void* __restrict__ outv, int O) {
    extern __shared__ float sm[];

    const int tid = threadIdx.x;
    const int wid = tid >> 5, lane = tid & 31;
    const int gid = lane >> 2, tg = lane & 3;
    const int warp_m = (wid & 3) * 32, warp_n = (wid >> 2) * 64;

    const int t0 = blockIdx.x * 128, o0 = blockIdx.y * 128, z = blockIdx.z;
    const uint32_t* Xb = Xp + (size_t)z * 512 * 1024;

    float c[2][8][4];
#pragma unroll
    for (int mt = 0; mt < 2; mt++)
#pragma unroll
        for (int nt = 0; nt < 8; nt++)
#pragma unroll
            for (int e = 0; e < 4; e++) c[mt][nt][e] = 0.f;

    const uint32_t aS = smem_u32(sm);
    const int lrow = lane & 15, lkw = (lane >> 4) * 4;

    auto issue = [&](int s, int kt) {
        const int k0 = kt * 32;
        const int kp0 = kt * 16;
        uint32_t bA = aS + (uint32_t)(s * STG_W * 4);
        uint32_t bB = bA + (uint32_t)(128 * APW * 4);
#pragma unroll
        for (int i = 0; i < 2; i++) {
            int id = tid * 2 + i;
            int row = id >> 2, gr = id & 3;
            cp16(bA + (uint32_t)(row * APW * 4 + gr * 16),
                 Wb + (size_t)(o0 + row) * 1024 + k0 + gr * 8);
        }
#pragma unroll
        for (int i = 0; i < 2; i++) {
            int id = tid * 2 + i;
            int row = id >> 5, gw = id & 31;
            cp16(bB + (uint32_t)(row * BPW * 4 + gw * 16),
                 Xb + (size_t)(kp0 + row) * 1024 + t0 + gw * 4);
        }
        cp_commit();
    };

    issue(0, 0);
    issue(1, 1);

    int stage = 0;
    for (int kt = 0; kt < 32; kt++) {
        if (kt + 1 < 32) cp_wait1(); else cp_wait0();
        __syncthreads();
        if (kt + 2 < 32) issue(stage == 0 ? 2 : stage - 1, kt + 2);

        const uint32_t aWb = aS + (uint32_t)(stage * STG_W * 4);
        const uint32_t* xb = (const uint32_t*)sm + stage * STG_W + 128 * APW;

#pragma unroll
        for (int ks = 0; ks < 2; ks++) {
            const int kw = ks * 8;
            uint32_t af[2][4];
#pragma unroll
            for (int mt = 0; mt < 2; mt++) {
                uint32_t addr = aWb +
                    (uint32_t)(((warp_m + mt * 16 + lrow) * APW + kw + lkw) * 4);
                ldsm_x4(af[mt], addr);
            }
            uint32_t bf[8][2];
#pragma unroll
            for (int nt = 0; nt < 8; nt++) {
                const uint32_t* xr = xb + (kw + tg) * BPW + warp_n + nt * 8 + gid;
                bf[nt][0] = xr[0];
                bf[nt][1] = xr[4 * BPW];
            }
#pragma unroll
            for (int mt = 0; mt < 2; mt++)
#pragma unroll
                for (int nt = 0; nt < 8; nt++)
                    mma_bf16(c[mt][nt], af[mt], bf[nt]);
        }
        stage = (stage == 2) ? 0 : stage + 1;
    }

#pragma unroll
    for (int mt = 0; mt < 2; mt++) {
#pragma unroll
        for (int half = 0; half < 2; half++) {
            int o = o0 + warp_m + mt * 16 + gid + half * 8;
            float bv = bias[o];
            size_t rowbase = ((size_t)z * O + o) * 1024;
#pragma unroll
            for (int nt = 0; nt < 8; nt++) {
                int t = t0 + warp_n + nt * 8 + tg * 2;
                float vx = c[mt][nt][half * 2 + 0] + bv;
                float vy = c[mt][nt][half * 2 + 1] + bv;
                if (BF16OUT) {
                    ((uint32_t*)outv)[(rowbase + t) >> 1] = bfpack(vx, vy);
                } else {
                    float2 rr = *(const float2*)(R + rowbase + t);
                    float2 v = { vx + rr.x, vy + rr.y };
                    *(float2*)((float*)outv + rowbase + t) = v;
                }
            }
        }
    }
}

// ---------------------------------------------------------------------------
// Flash attention, bf16 mma, Q-tile 128, double-buffered K/V in smem:
// ONE __syncthreads per 64-key tile.
// ---------------------------------------------------------------------------
#define TPW 36
#define ATTN_SMEM (512 * TPW * 4)

__global__ __launch_bounds__(256, 2) void attn_mma(const uint16_t* __restrict__ qkvb,
                                                   uint32_t* __restrict__ attnp) {
    extern __shared__ float smf[];
    uint32_t* Qt = (uint32_t*)smf;          // [128 i][TPW]
    uint32_t* St = Qt + 128 * TPW;          // [128 i][TPW]
    uint32_t* Kt = St + 128 * TPW;          // [2][64 j][TPW]
    uint32_t* Vs = Kt + 128 * TPW;          // [2][64 c][TPW]

    const int bh = blockIdx.y;
    const int b = bh >> 4, h = bh & 15;
    const int t0 = blockIdx.x * 128;
    const uint16_t* qg = qkvb + ((size_t)b * 3072 + h * 192) * 1024;
    const uint16_t* kg = qg + 64 * 1024;
    const uint32_t* vg = (const uint32_t*)(qg + 128 * 1024);

    const int tid = threadIdx.x, wid = tid >> 5, lane = tid & 31;
    const int gid = lane >> 2, tg = lane & 3;
    const int i0 = wid * 16;

    const uint32_t aQt = smem_u32(Qt), aKt = smem_u32(Kt);
    const uint32_t aVs = smem_u32(Vs), aSt = smem_u32(St);
    const int lrow = lane & 15, lkw = (lane >> 4) * 4;
    const uint32_t bOffB = (uint32_t)(((i0 + ((lane >> 4) << 3) + (lane & 7)) * TPW
                                       + ((lane >> 3) & 1) * 4) * 4);

    // Q tile: Qt[i][cpair], 128 rows
#pragma unroll
    for (int r = 0; r < 16; r++) {
        int u = r * 256 + tid;
        int i = u & 127, cp = u >> 7;
        uint32_t lo = qg[(size_t)(2 * cp) * 1024 + t0 + i];
        uint32_t hi = qg[(size_t)(2 * cp + 1) * 1024 + t0 + i];
        Qt[i * TPW + cp] = lo | (hi << 16);
    }

    uint32_t kwr[8], vwr[8];
    auto ldg_tile = [&](int s0) {
#pragma unroll
        for (int r = 0; r < 8; r++) {
            int u = r * 256 + tid;
            int j = u & 63, cp = u >> 6;
            uint32_t lo = kg[(size_t)(2 * cp) * 1024 + s0 + j];
            uint32_t hi = kg[(size_t)(2 * cp + 1) * 1024 + s0 + j];
            kwr[r] = lo | (hi << 16);
            int cc = u >> 5, jw = u & 31;
            vwr[r] = vg[((size_t)cc * 1024 + s0) / 2 + jw];
        }
    };
    auto store_kv = [&](int buf) {
        uint32_t* kb = Kt + buf * 64 * TPW;
        uint32_t* vb = Vs + buf * 64 * TPW;
#pragma unroll
        for (int r = 0; r < 8; r++) {
            int u = r * 256 + tid;
            int j = u & 63, cp = u >> 6;
            kb[j * TPW + cp] = kwr[r];
            int cc = u >> 5, jw = u & 31;
            vb[cc * TPW + jw] = vwr[r];
        }
    };

    float o[2][4][4];
#pragma unroll
    for (int q = 0; q < 2; q++)
#pragma unroll
        for (int mt = 0; mt < 4; mt++)
#pragma unroll
            for (int e = 0; e < 4; e++) o[q][mt][e] = 0.f;
    float m_run[2][2] = { { -1e30f, -1e30f }, { -1e30f, -1e30f } };
    float l_run[2][2] = { { 0.f, 0.f }, { 0.f, 0.f } };

    ldg_tile(0);
    store_kv(0);
    __syncthreads();

    for (int t = 0; t < 16; t++) {
        const int buf = t & 1;
        const uint32_t kOff = (uint32_t)(buf * 64 * TPW * 4);
        if (t + 1 < 16) ldg_tile((t + 1) * 64);

        // ---- S = Kt * Q ----
        float sc[2][4][4];
#pragma unroll
        for (int q = 0; q < 2; q++)
#pragma unroll
            for (int mt = 0; mt < 4; mt++)
#pragma unroll
                for (int e = 0; e < 4; e++) sc[q][mt][e] = 0.f;

#pragma unroll
        for (int ks = 0; ks < 4; ks++) {
            uint32_t bb[4];
            ldsm_x4(bb, aQt + bOffB + (uint32_t)(ks * 32));
#pragma unroll
            for (int mt = 0; mt < 4; mt++) {
                uint32_t a[4];
                ldsm_x4(a, aKt + kOff + (uint32_t)(((mt * 16 + lrow) * TPW + lkw) * 4 + ks * 32));
                mma_bf16(sc[0][mt], a, bb);
                mma_bf16(sc[1][mt], a, bb + 2);
            }
        }

        // ---- warp-local online softmax ----
        float alpha[2][2], psum[2][2];
#pragma unroll
        for (int q = 0; q < 2; q++) {
#pragma unroll
            for (int e = 0; e < 2; e++) {
                float cm = fmaxf(fmaxf(sc[q][0][e], sc[q][0][e + 2]),
                                 fmaxf(sc[q][1][e], sc[q][1][e + 2]));
                cm = fmaxf(cm, fmaxf(fmaxf(sc[q][2][e], sc[q][2][e + 2]),
                                     fmaxf(sc[q][3][e], sc[q][3][e + 2])));
                cm *= 0.125f;
#pragma unroll
                for (int mk = 4; mk <= 16; mk <<= 1)
                    cm = fmaxf(cm, __shfl_xor_sync(0xffffffffu, cm, mk));
                float mn = fmaxf(m_run[q][e], cm);
                alpha[q][e] = __expf(m_run[q][e] - mn);
                m_run[q][e] = mn;
                psum[q][e] = 0.f;
            }
        }
#pragma unroll
        for (int q = 0; q < 2; q++) {
#pragma unroll
            for (int mt = 0; mt < 4; mt++) {
#pragma unroll
                for (int e = 0; e < 2; e++) {
                    uint32_t h0 = bfu(__expf(sc[q][mt][e] * 0.125f - m_run[q][e]));
                    uint32_t h1 = bfu(__expf(sc[q][mt][e + 2] * 0.125f - m_run[q][e]));
                    psum[q][e] += ubf(h0) + ubf(h1);
                    uint32_t w = h0 | (h1 << 16);
                    uint32_t pw = __shfl_xor_sync(0xffffffffu, w, 4);
                    if ((gid & 1) == 0) {
                        int i = i0 + 8 * q + 2 * tg + e;
                        St[i * TPW + (mt * 16 + gid) / 2] = (w & 0xffffu) | (pw << 16);
                        St[i * TPW + (mt * 16 + gid + 8) / 2] = (w >> 16) | (pw & 0xffff0000u);
                    }
                }
            }
        }
#pragma unroll
        for (int q = 0; q < 2; q++) {
#pragma unroll
            for (int e = 0; e < 2; e++) {
#pragma unroll
                for (int mk = 4; mk <= 16; mk <<= 1)
                    psum[q][e] += __shfl_xor_sync(0xffffffffu, psum[q][e], mk);
                l_run[q][e] = l_run[q][e] * alpha[q][e] + psum[q][e];
            }
#pragma unroll
            for (int mt = 0; mt < 4; mt++) {
                o[q][mt][0] *= alpha[q][0]; o[q][mt][2] *= alpha[q][0];
                o[q][mt][1] *= alpha[q][1]; o[q][mt][3] *= alpha[q][1];
            }
        }
        __syncwarp();

        // ---- O += V * P ----
#pragma unroll
        for (int ks = 0; ks < 4; ks++) {
            uint32_t bb[4];
            ldsm_x4(bb, aSt + bOffB + (uint32_t)(ks * 32));
#pragma unroll
            for (int mt = 0; mt < 4; mt++) {
                uint32_t a[4];
                ldsm_x4(a, aVs + kOff + (uint32_t)(((mt * 16 + lrow) * TPW + lkw) * 4 + ks * 32));
                mma_bf16(o[0][mt], a, bb);
                mma_bf16(o[1][mt], a, bb + 2);
            }
        }

        if (t + 1 < 16) store_kv(buf ^ 1);
        __syncthreads();
    }

    // normalize + write packed bf16 pairs over c
#pragma unroll
    for (int q = 0; q < 2; q++) {
        float li0 = 1.f / l_run[q][0], li1 = 1.f / l_run[q][1];
#pragma unroll
        for (int mt = 0; mt < 4; mt++) {
#pragma unroll
            for (int e = 0; e < 2; e++) {
                float li = e ? li1 : li0;
                uint32_t b0 = bfu(o[q][mt][e] * li);
                uint32_t b1 = bfu(o[q][mt][e + 2] * li);
                uint32_t w = b0 | (b1 << 16);
                uint32_t pw = __shfl_xor_sync(0xffffffffu, w, 4);
                if ((gid & 1) == 0) {
                    int i = t0 + i0 + 8 * q + 2 * tg + e;
                    int c = h * 64 + mt * 16 + gid;
                    attnp[((size_t)b * 512 + c / 2) * 1024 + i] = (w & 0xffffu) | (pw << 16);
                    attnp[((size_t)b * 512 + (c + 8) / 2) * 1024 + i] = (w >> 16) | (pw & 0xffff0000u);
                }
            }
        }
    }
}

// ---------------------------------------------------------------------------
extern "C" void kernel_launch(void* const* d_in, const int* in_sizes, int n_in,
                              void* d_out, int out_size) {
    const float* x      = (const float*)d_in[0];
    const float* nw     = (const float*)d_in[1];
    const float* nb     = (const float*)d_in[2];
    const float* qkv_w  = (const float*)d_in[3];
    const float* qkv_b  = (const float*)d_in[4];
    const float* proj_w = (const float*)d_in[5];
    const float* proj_b = (const float*)d_in[6];
    float* out = (float*)d_out;

    uint16_t *wq, *wp, *qkvb;
    uint32_t *xnp, *attnp;
    cudaGetSymbolAddress((void**)&wq,    g_wq);
    cudaGetSymbolAddress((void**)&wp,    g_wp);
    cudaGetSymbolAddress((void**)&xnp,   g_xnp);
    cudaGetSymbolAddress((void**)&qkvb,  g_qkvb);
    cudaGetSymbolAddress((void**)&attnp, g_attnp);

    // 0. Weight conversion to bf16 (both in one launch)
    conv_w2<<<4096, 256>>>(qkv_w, (uint32_t*)wq, 786432, proj_w, (uint32_t*)wp);

    // 1. GroupNorm -> packed bf16
    gn_kernel<<<128, 1024>>>(x, nw, nb, xnp);

    // 2. QKV projection (bf16 mma, 3-stage) -> bf16
    cudaFuncSetAttribute(gemm_bf16<true>, cudaFuncAttributeMaxDynamicSharedMemorySize, GEMM_SMEM);
    gemm_bf16<true><<<dim3(8, 24, 4), 256, GEMM_SMEM>>>(wq, xnp, qkv_b, nullptr, qkvb, 3072);

    // 3. Attention (bf16 mma flash, Q-tile 128, 1 sync/tile) -> packed bf16
    cudaFuncSetAttribute(attn_mma, cudaFuncAttributeMaxDynamicSharedMemorySize, ATTN_SMEM);
    attn_mma<<<dim3(8, 64), 256, ATTN_SMEM>>>(qkvb, attnp);

    // 4. Output projection + bias + residual (fp32 out)
    cudaFuncSetAttribute(gemm_bf16<false>, cudaFuncAttributeMaxDynamicSharedMemorySize, GEMM_SMEM);
    gemm_bf16<false><<<dim3(8, 8, 4), 256, GEMM_SMEM>>>(wp, attnp, proj_b, x, out, 1024);
}

// round 16
// speedup vs baseline: 1.2513x; 1.1975x over previous
#include <cuda_runtime.h>
#include <cuda_bf16.h>
#include <math.h>
#include <stdint.h>

// ---------------------------------------------------------------------------
// Scratch (device globals; no dynamic allocation allowed)
// ---------------------------------------------------------------------------
__device__ uint16_t g_wq[3072 * 1024];        // qkv_w  bf16 [o][k]
__device__ uint16_t g_wp[1024 * 1024];        // proj_w bf16 [o][k]
__device__ uint32_t g_xnp[4 * 512 * 1024];    // xn  packed bf16 pairs [b][c/2][t]
__device__ uint16_t g_qkvb[4 * 3072 * 1024];  // qkv bf16 [b][3C][t]
__device__ uint32_t g_attnp[4 * 512 * 1024];  // attn packed bf16 pairs [b][c/2][t]

// ---------------------------------------------------------------------------
// helpers
// ---------------------------------------------------------------------------
__device__ __forceinline__ uint32_t smem_u32(const void* p) {
    uint32_t a;
    asm("{ .reg .u64 t; cvta.to.shared.u64 t, %1; cvt.u32.u64 %0, t; }" : "=r"(a) : "l"(p));
    return a;
}
__device__ __forceinline__ uint32_t bfpack(float lo, float hi) {
    uint32_t r;
    asm("cvt.rn.bf16x2.f32 %0, %1, %2;" : "=r"(r) : "f"(hi), "f"(lo));
    return r;
}
__device__ __forceinline__ float ubf(uint32_t bits16) {
    return __uint_as_float(bits16 << 16);
}
__device__ __forceinline__ void cp16(uint32_t dst, const void* src) {
    asm volatile("cp.async.cg.shared.global [%0], [%1], 16;" :: "r"(dst), "l"(src));
}
__device__ __forceinline__ void cp_commit() { asm volatile("cp.async.commit_group;"); }
__device__ __forceinline__ void cp_wait0() { asm volatile("cp.async.wait_group 0;" ::: "memory"); }
__device__ __forceinline__ void cp_wait1() { asm volatile("cp.async.wait_group 1;" ::: "memory"); }

// bf16 MMA m16n8k16
__device__ __forceinline__ void mma_bf16(float* c, const uint32_t* a, const uint32_t* b) {
    asm volatile(
        "mma.sync.aligned.m16n8k16.row.col.f32.bf16.bf16.f32 "
        "{%0,%1,%2,%3}, {%4,%5,%6,%7}, {%8,%9}, {%0,%1,%2,%3};"
        : "+f"(c[0]), "+f"(c[1]), "+f"(c[2]), "+f"(c[3])
        : "r"(a[0]), "r"(a[1]), "r"(a[2]), "r"(a[3]), "r"(b[0]), "r"(b[1]));
}
__device__ __forceinline__ void ldsm_x4(uint32_t* r, uint32_t addr) {
    asm volatile("ldmatrix.sync.aligned.m8n8.x4.shared.b16 {%0,%1,%2,%3}, [%4];"
                 : "=r"(r[0]), "=r"(r[1]), "=r"(r[2]), "=r"(r[3]) : "r"(addr));
}

// ---------------------------------------------------------------------------
// Weight conversion fp32 -> bf16 (both weights in one launch)
// ---------------------------------------------------------------------------
__global__ void conv_w2(const float* __restrict__ s1, uint32_t* __restrict__ d1, int n1,
                        const float* __restrict__ s2, uint32_t* __restrict__ d2) {
    int i = blockIdx.x * 256 + threadIdx.x;
    const float4* src;
    uint2* dst;
    int j;
    if (i < n1) { src = (const float4*)s1; dst = (uint2*)d1; j = i; }
    else        { src = (const float4*)s2; dst = (uint2*)d2; j = i - n1; }
    float4 v = src[j];
    uint2 o;
    o.x = bfpack(v.x, v.y);
    o.y = bfpack(v.z, v.w);
    dst[j] = o;
}

// ---------------------------------------------------------------------------
// GroupNorm: one block per (batch, group); writes c-pair-packed bf16.
// ---------------------------------------------------------------------------
__global__ __launch_bounds__(1024) void gn_kernel(const float* __restrict__ x,
                                                  const float* __restrict__ w,
                                                  const float* __restrict__ b,
                                                  uint32_t* __restrict__ xnp) {
    int batch = blockIdx.x >> 5;
    int g = blockIdx.x & 31;
    const float4* xp = (const float4*)(x + ((size_t)batch * 1024 + g * 32) * 1024);

    float4 va[4], vb[4];
    float s = 0.f, ss = 0.f;
#pragma unroll
    for (int r = 0; r < 4; r++) {
        int u = r * 1024 + threadIdx.x;
        int cp = u >> 8, t4 = u & 255;
        va[r] = xp[cp * 512 + t4];
        vb[r] = xp[cp * 512 + 256 + t4];
        s += va[r].x + va[r].y + va[r].z + va[r].w + vb[r].x + vb[r].y + vb[r].z + vb[r].w;
        ss += va[r].x * va[r].x + va[r].y * va[r].y + va[r].z * va[r].z + va[r].w * va[r].w
            + vb[r].x * vb[r].x + vb[r].y * vb[r].y + vb[r].z * vb[r].z + vb[r].w * vb[r].w;
    }
#pragma unroll
    for (int o = 16; o; o >>= 1) {
        s  += __shfl_xor_sync(0xffffffffu, s, o);
        ss += __shfl_xor_sync(0xffffffffu, ss, o);
    }
    __shared__ float red[66];
    int warp = threadIdx.x >> 5, lane = threadIdx.x & 31;
    if (lane == 0) { red[warp] = s; red[warp + 32] = ss; }
    __syncthreads();
    if (threadIdx.x == 0) {
        float ts = 0.f, tss = 0.f;
#pragma unroll
        for (int i = 0; i < 32; i++) { ts += red[i]; tss += red[i + 32]; }
        float mu = ts * (1.f / 32768.f);
        float var = tss * (1.f / 32768.f) - mu * mu;
        red[64] = mu;
        red[65] = rsqrtf(var + 1e-5f);
    }
    __syncthreads();
    float mu = red[64], inv = red[65];
#pragma unroll
    for (int r = 0; r < 4; r++) {
        int u = r * 1024 + threadIdx.x;
        int cp = u >> 8, t4 = u & 255;
        int c0 = g * 32 + 2 * cp, c1 = c0 + 1;
        float s0 = inv * w[c0], h0 = b[c0] - mu * s0;
        float s1 = inv * w[c1], h1 = b[c1] - mu * s1;
        uint4 o;
        o.x = bfpack(va[r].x * s0 + h0, vb[r].x * s1 + h1);
        o.y = bfpack(va[r].y * s0 + h0, vb[r].y * s1 + h1);
        o.z = bfpack(va[r].z * s0 + h0, vb[r].z * s1 + h1);
        o.w = bfpack(va[r].w * s0 + h0, vb[r].w * s1 + h1);
        ((uint4*)(xnp + ((size_t)(batch * 512 + g * 16 + cp)) * 1024))[t4] = o;
    }
}

// ---------------------------------------------------------------------------
// bf16 tensor-core GEMM: K-tile 32, ldmatrix A fragments, 3-stage cp.async
// ring with ONE __syncthreads per k-tile. (R13 configuration, best measured.)
// ---------------------------------------------------------------------------
#define APW 20
#define BPW 136
#define STG_W (128 * APW + 16 * BPW)
#define GEMM_SMEM (3 * STG_W * 4)

template <bool BF16OUT>
__global__ __launch_bounds__(256, 2) void gemm_bf16(const uint16_t* __restrict__ Wb,
                                                    const uint32_t* __restrict__ Xp,
                                                    const float* __restrict__ bias,
                                                    const float* __restrict__ R,
                                                    void* __restrict__ outv, int O) {
    extern __shared__ float sm[];

    const int tid = threadIdx.x;
    const int wid = tid >> 5, lane = tid & 31;
    const int gid = lane >> 2, tg = lane & 3;
    const int warp_m = (wid & 3) * 32, warp_n = (wid >> 2) * 64;

    const int t0 = blockIdx.x * 128, o0 = blockIdx.y * 128, z = blockIdx.z;
    const uint32_t* Xb = Xp + (size_t)z * 512 * 1024;

    float c[2][8][4];
#pragma unroll
    for (int mt = 0; mt < 2; mt++)
#pragma unroll
        for (int nt = 0; nt < 8; nt++)
#pragma unroll
            for (int e = 0; e < 4; e++) c[mt][nt][e] = 0.f;

    const uint32_t aS = smem_u32(sm);
    const int lrow = lane & 15, lkw = (lane >> 4) * 4;

    auto issue = [&](int s, int kt) {
        const int k0 = kt * 32;
        const int kp0 = kt * 16;
        uint32_t bA = aS + (uint32_t)(s * STG_W * 4);
        uint32_t bB = bA + (uint32_t)(128 * APW * 4);
#pragma unroll
        for (int i = 0; i < 2; i++) {
            int id = tid * 2 + i;
            int row = id >> 2, gr = id & 3;
            cp16(bA + (uint32_t)(row * APW * 4 + gr * 16),
                 Wb + (size_t)(o0 + row) * 1024 + k0 + gr * 8);
        }
#pragma unroll
        for (int i = 0; i < 2; i++) {
            int id = tid * 2 + i;
            int row = id >> 5, gw = id & 31;
            cp16(bB + (uint32_t)(row * BPW * 4 + gw * 16),
                 Xb + (size_t)(kp0 + row) * 1024 + t0 + gw * 4);
        }
        cp_commit();
    };

    issue(0, 0);
    issue(1, 1);

    int stage = 0;
    for (int kt = 0; kt < 32; kt++) {
        if (kt + 1 < 32) cp_wait1(); else cp_wait0();
        __syncthreads();
        if (kt + 2 < 32) issue(stage == 0 ? 2 : stage - 1, kt + 2);

        const uint32_t aWb = aS + (uint32_t)(stage * STG_W * 4);
        const uint32_t* xb = (const uint32_t*)sm + stage * STG_W + 128 * APW;

#pragma unroll
        for (int ks = 0; ks < 2; ks++) {
            const int kw = ks * 8;
            uint32_t af[2][4];
#pragma unroll
            for (int mt = 0; mt < 2; mt++) {
                uint32_t addr = aWb +
                    (uint32_t)(((warp_m + mt * 16 + lrow) * APW + kw + lkw) * 4);
                ldsm_x4(af[mt], addr);
            }
            uint32_t bf[8][2];
#pragma unroll
            for (int nt = 0; nt < 8; nt++) {
                const uint32_t* xr = xb + (kw + tg) * BPW + warp_n + nt * 8 + gid;
                bf[nt][0] = xr[0];
                bf[nt][1] = xr[4 * BPW];
            }
#pragma unroll
            for (int mt = 0; mt < 2; mt++)
#pragma unroll
                for (int nt = 0; nt < 8; nt++)
                    mma_bf16(c[mt][nt], af[mt], bf[nt]);
        }
        stage = (stage == 2) ? 0 : stage + 1;
    }

#pragma unroll
    for (int mt = 0; mt < 2; mt++) {
#pragma unroll
        for (int half = 0; half < 2; half++) {
            int o = o0 + warp_m + mt * 16 + gid + half * 8;
            float bv = bias[o];
            size_t rowbase = ((size_t)z * O + o) * 1024;
#pragma unroll
            for (int nt = 0; nt < 8; nt++) {
                int t = t0 + warp_n + nt * 8 + tg * 2;
                float vx = c[mt][nt][half * 2 + 0] + bv;
                float vy = c[mt][nt][half * 2 + 1] + bv;
                if (BF16OUT) {
                    ((uint32_t*)outv)[(rowbase + t) >> 1] = bfpack(vx, vy);
                } else {
                    float2 rr = *(const float2*)(R + rowbase + t);
                    float2 v = { vx + rr.x, vy + rr.y };
                    *(float2*)((float*)outv + rowbase + t) = v;
                }
            }
        }
    }
}

// ---------------------------------------------------------------------------
// Flash attention, FA2-style: P stays in registers.
//   S = Q K^T : A = Qt rows (warp's 16 i), B = Kt[j][cpair]
//   O = P V   : A = packed S fragments (registers), B = Vs[c][jpair]
// Q-tile 128, double-buffered K/V, one __syncthreads per 64-key tile.
// ---------------------------------------------------------------------------
#define TPW 36
#define ATTN_SMEM (384 * TPW * 4)

__global__ __launch_bounds__(256, 2) void attn_mma(const uint16_t* __restrict__ qkvb,
                                                   uint32_t* __restrict__ attnp) {
    extern __shared__ float smf[];
    uint32_t* Qt = (uint32_t*)smf;          // [128 i][TPW]  c-pair packed
    uint32_t* Kt = Qt + 128 * TPW;          // [2][64 j][TPW] c-pair packed
    uint32_t* Vs = Kt + 128 * TPW;          // [2][64 c][TPW] j-pair packed (natural)

    const int bh = blockIdx.y;
    const int b = bh >> 4, h = bh & 15;
    const int t0 = blockIdx.x * 128;
    const uint16_t* qg = qkvb + ((size_t)b * 3072 + h * 192) * 1024;
    const uint16_t* kg = qg + 64 * 1024;
    const uint32_t* vg = (const uint32_t*)(qg + 128 * 1024);

    const int tid = threadIdx.x, wid = tid >> 5, lane = tid & 31;
    const int gid = lane >> 2, tg = lane & 3;
    const int i0 = wid * 16;

    const uint32_t aQt = smem_u32(Qt), aKt = smem_u32(Kt), aVs = smem_u32(Vs);
    const int lrow = lane & 15, lkw = (lane >> 4) * 4;
    // B-operand ldmatrix.x4 per 16-row group: m0/m1 = rows r0..r0+7 (words w/w+4),
    // m2/m3 = rows r0+8..r0+15.
    const int bRow = ((lane >> 4) << 3) + (lane & 7);
    const int bWrd = ((lane >> 3) & 1) * 4;

    // Q tile: Qt[i][cpair], 128 rows
#pragma unroll
    for (int r = 0; r < 16; r++) {
        int u = r * 256 + tid;
        int i = u & 127, cp = u >> 7;
        uint32_t lo = qg[(size_t)(2 * cp) * 1024 + t0 + i];
        uint32_t hi = qg[(size_t)(2 * cp + 1) * 1024 + t0 + i];
        Qt[i * TPW + cp] = lo | (hi << 16);
    }

    uint32_t kwr[8], vwr[8];
    auto ldg_tile = [&](int s0) {
#pragma unroll
        for (int r = 0; r < 8; r++) {
            int u = r * 256 + tid;
            int j = u & 63, cp = u >> 6;
            uint32_t lo = kg[(size_t)(2 * cp) * 1024 + s0 + j];
            uint32_t hi = kg[(size_t)(2 * cp + 1) * 1024 + s0 + j];
            kwr[r] = lo | (hi << 16);
            int cc = u >> 5, jw = u & 31;
            vwr[r] = vg[((size_t)cc * 1024 + s0) / 2 + jw];
        }
    };
    auto store_kv = [&](int buf) {
        uint32_t* kb = Kt + buf * 64 * TPW;
        uint32_t* vb = Vs + buf * 64 * TPW;
#pragma unroll
        for (int r = 0; r < 8; r++) {
            int u = r * 256 + tid;
            int j = u & 63, cp = u >> 6;
            kb[j * TPW + cp] = kwr[r];
            int cc = u >> 5, jw = u & 31;
            vb[cc * TPW + jw] = vwr[r];
        }
    };

    float o[8][4];
#pragma unroll
    for (int nc = 0; nc < 8; nc++)
#pragma unroll
        for (int e = 0; e < 4; e++) o[nc][e] = 0.f;
    float m_run[2] = { -1e30f, -1e30f };   // rows gid, gid+8
    float l_run[2] = { 0.f, 0.f };

    ldg_tile(0);
    store_kv(0);
    __syncthreads();

    for (int t = 0; t < 16; t++) {
        const int buf = t & 1;
        const uint32_t kOff = (uint32_t)(buf * 64 * TPW * 4);
        if (t + 1 < 16) ldg_tile((t + 1) * 64);

        // ---- S = Q K^T : rows i0..i0+15, all 64 j ----
        float sc[8][4];
#pragma unroll
        for (int nj = 0; nj < 8; nj++)
#pragma unroll
            for (int e = 0; e < 4; e++) sc[nj][e] = 0.f;

#pragma unroll
        for (int ks = 0; ks < 4; ks++) {
            uint32_t a[4];
            ldsm_x4(a, aQt + (uint32_t)(((i0 + lrow) * TPW + lkw) * 4 + ks * 32));
#pragma unroll
            for (int jj = 0; jj < 4; jj++) {
                uint32_t bb[4];
                ldsm_x4(bb, aKt + kOff +
                        (uint32_t)(((jj * 16 + bRow) * TPW + bWrd) * 4 + ks * 32));
                mma_bf16(sc[2 * jj], a, bb);
                mma_bf16(sc[2 * jj + 1], a, bb + 2);
            }
        }

        // ---- row-wise online softmax (rows gid, gid+8) ----
        float cm0 = -1e30f, cm1 = -1e30f;
#pragma unroll
        for (int nj = 0; nj < 8; nj++) {
            cm0 = fmaxf(cm0, fmaxf(sc[nj][0], sc[nj][1]));
            cm1 = fmaxf(cm1, fmaxf(sc[nj][2], sc[nj][3]));
        }
        cm0 *= 0.125f; cm1 *= 0.125f;
        cm0 = fmaxf(cm0, __shfl_xor_sync(0xffffffffu, cm0, 1));
        cm0 = fmaxf(cm0, __shfl_xor_sync(0xffffffffu, cm0, 2));
        cm1 = fmaxf(cm1, __shfl_xor_sync(0xffffffffu, cm1, 1));
        cm1 = fmaxf(cm1, __shfl_xor_sync(0xffffffffu, cm1, 2));
        float mn0 = fmaxf(m_run[0], cm0), mn1 = fmaxf(m_run[1], cm1);
        float al0 = __expf(m_run[0] - mn0), al1 = __expf(m_run[1] - mn1);
        m_run[0] = mn0; m_run[1] = mn1;

        // exp, pack P into A fragments (registers), partial sums
        uint32_t pa[4][4];
        float ps0 = 0.f, ps1 = 0.f;
#pragma unroll
        for (int jc = 0; jc < 4; jc++) {
#pragma unroll
            for (int half = 0; half < 2; half++) {
                int nj = 2 * jc + half;
                uint32_t w0 = bfpack(__expf(sc[nj][0] * 0.125f - mn0),
                                     __expf(sc[nj][1] * 0.125f - mn0));
                uint32_t w1 = bfpack(__expf(sc[nj][2] * 0.125f - mn1),
                                     __expf(sc[nj][3] * 0.125f - mn1));
                pa[jc][half * 2] = w0;       // rows gid:   a0 (half=0), a2 (half=1)
                pa[jc][half * 2 + 1] = w1;   // rows gid+8: a1 (half=0), a3 (half=1)
                ps0 += ubf(w0 & 0xffffu) + ubf(w0 >> 16);
                ps1 += ubf(w1 & 0xffffu) + ubf(w1 >> 16);
            }
        }
        ps0 += __shfl_xor_sync(0xffffffffu, ps0, 1);
        ps0 += __shfl_xor_sync(0xffffffffu, ps0, 2);
        ps1 += __shfl_xor_sync(0xffffffffu, ps1, 1);
        ps1 += __shfl_xor_sync(0xffffffffu, ps1, 2);
        l_run[0] = l_run[0] * al0 + ps0;
        l_run[1] = l_run[1] * al1 + ps1;

        // rescale O
#pragma unroll
        for (int nc = 0; nc < 8; nc++) {
            o[nc][0] *= al0; o[nc][1] *= al0;
            o[nc][2] *= al1; o[nc][3] *= al1;
        }

        // ---- O += P V : A = pa (registers), B = Vs ----
#pragma unroll
        for (int jc = 0; jc < 4; jc++) {
#pragma unroll
            for (int cc = 0; cc < 4; cc++) {
                uint32_t bb[4];
                ldsm_x4(bb, aVs + kOff +
                        (uint32_t)(((cc * 16 + bRow) * TPW + bWrd) * 4 + jc * 32));
                mma_bf16(o[2 * cc], pa[jc], bb);
                mma_bf16(o[2 * cc + 1], pa[jc], bb + 2);
            }
        }

        if (t + 1 < 16) store_kv(buf ^ 1);
        __syncthreads();
    }

    // normalize + write: row i = t0+i0+gid (+8), c pair = 8nc+2tg
    float li0 = 1.f / l_run[0], li1 = 1.f / l_run[1];
#pragma unroll
    for (int nc = 0; nc < 8; nc++) {
        int cpair = h * 32 + 4 * nc + tg;
        size_t base = ((size_t)b * 512 + cpair) * 1024 + t0 + i0 + gid;
        attnp[base] = bfpack(o[nc][0] * li0, o[nc][1] * li0);
        attnp[base + 8] = bfpack(o[nc][2] * li1, o[nc][3] * li1);
    }
}

// ---------------------------------------------------------------------------
extern "C" void kernel_launch(void* const* d_in, const int* in_sizes, int n_in,
                              void* d_out, int out_size) {
    const float* x      = (const float*)d_in[0];
    const float* nw     = (const float*)d_in[1];
    const float* nb     = (const float*)d_in[2];
    const float* qkv_w  = (const float*)d_in[3];
    const float* qkv_b  = (const float*)d_in[4];
    const float* proj_w = (const float*)d_in[5];
    const float* proj_b = (const float*)d_in[6];
    float* out = (float*)d_out;

    uint16_t *wq, *wp, *qkvb;
    uint32_t *xnp, *attnp;
    cudaGetSymbolAddress((void**)&wq,    g_wq);
    cudaGetSymbolAddress((void**)&wp,    g_wp);
    cudaGetSymbolAddress((void**)&xnp,   g_xnp);
    cudaGetSymbolAddress((void**)&qkvb,  g_qkvb);
    cudaGetSymbolAddress((void**)&attnp, g_attnp);

    // 0. Weight conversion to bf16 (both in one launch)
    conv_w2<<<4096, 256>>>(qkv_w, (uint32_t*)wq, 786432, proj_w, (uint32_t*)wp);

    // 1. GroupNorm -> packed bf16
    gn_kernel<<<128, 1024>>>(x, nw, nb, xnp);

    // 2. QKV projection (bf16 mma, 3-stage) -> bf16
    cudaFuncSetAttribute(gemm_bf16<true>, cudaFuncAttributeMaxDynamicSharedMemorySize, GEMM_SMEM);
    gemm_bf16<true><<<dim3(8, 24, 4), 256, GEMM_SMEM>>>(wq, xnp, qkv_b, nullptr, qkvb, 3072);

    // 3. Attention (bf16 mma flash, register-resident P) -> packed bf16
    cudaFuncSetAttribute(attn_mma, cudaFuncAttributeMaxDynamicSharedMemorySize, ATTN_SMEM);
    attn_mma<<<dim3(8, 64), 256, ATTN_SMEM>>>(qkvb, attnp);

    // 4. Output projection + bias + residual (fp32 out)
    cudaFuncSetAttribute(gemm_bf16<false>, cudaFuncAttributeMaxDynamicSharedMemorySize, GEMM_SMEM);
    gemm_bf16<false><<<dim3(8, 8, 4), 256, GEMM_SMEM>>>(wp, attnp, proj_b, x, out, 1024);
}